// round 11
// baseline (speedup 1.0000x reference)
#include <cuda_runtime.h>
#include <cuda_fp16.h>
#include <cstdint>

#define BATCH 8
#define SEQ   4096
#define DIM   1024
#define RNK   64
#define KB    128
#define NIT   (SEQ/KB)

// ---------------- global scratch ----------------
__device__ __align__(16) __half   g_P[BATCH * SEQ * RNK];
__device__ __align__(16) __half   g_Pt[BATCH * RNK * SEQ];
__device__ __align__(16) __half   g_xh[(size_t)BATCH * SEQ * DIM];
__device__ __align__(16) uint8_t  g_x8t[(size_t)BATCH * DIM * SEQ];   // e4m3 [b][d][s]
__device__ __align__(16) __half   g_Qt[RNK * DIM];
__device__ __align__(16) __half   g_W[BATCH * RNK * DIM];             // 32*ln2*Pk^T x
__device__ __align__(16) float    g_Wpart[4][BATCH * RNK * DIM];
__device__ __align__(16) float    g_csum[BATCH * DIM];
__device__ __align__(16) float    g_cpart[32][BATCH * DIM];

// ---------------- helpers ----------------
__device__ __forceinline__ uint32_t smem_u32(const void* p) {
    uint32_t a;
    asm("{ .reg .u64 t; cvta.to.shared.u64 t, %1; cvt.u32.u64 %0, t; }" : "=r"(a) : "l"(p));
    return a;
}
__device__ __forceinline__ void ldsm4(uint32_t* r, uint32_t a) {
    asm volatile("ldmatrix.sync.aligned.m8n8.x4.shared.b16 {%0,%1,%2,%3}, [%4];"
        : "=r"(r[0]), "=r"(r[1]), "=r"(r[2]), "=r"(r[3]) : "r"(a));
}
__device__ __forceinline__ void ldsm4t(uint32_t* r, uint32_t a) {
    asm volatile("ldmatrix.sync.aligned.m8n8.x4.trans.shared.b16 {%0,%1,%2,%3}, [%4];"
        : "=r"(r[0]), "=r"(r[1]), "=r"(r[2]), "=r"(r[3]) : "r"(a));
}
__device__ __forceinline__ void mma16816(float* d, const uint32_t* a, const uint32_t* b) {
    asm volatile(
        "mma.sync.aligned.m16n8k16.row.col.f32.f16.f16.f32 "
        "{%0,%1,%2,%3}, {%4,%5,%6,%7}, {%8,%9}, {%0,%1,%2,%3};"
        : "+f"(d[0]), "+f"(d[1]), "+f"(d[2]), "+f"(d[3])
        : "r"(a[0]), "r"(a[1]), "r"(a[2]), "r"(a[3]), "r"(b[0]), "r"(b[1]));
}
__device__ __forceinline__ void mma_f8(float* d, const uint32_t* a, uint32_t b0, uint32_t b1) {
    asm volatile(
        "mma.sync.aligned.m16n8k32.row.col.f32.e4m3.e4m3.f32 "
        "{%0,%1,%2,%3}, {%4,%5,%6,%7}, {%8,%9}, {%0,%1,%2,%3};"
        : "+f"(d[0]), "+f"(d[1]), "+f"(d[2]), "+f"(d[3])
        : "r"(a[0]), "r"(a[1]), "r"(a[2]), "r"(a[3]), "r"(b0), "r"(b1));
}
__device__ __forceinline__ uint32_t lds32(uint32_t a) {
    uint32_t v;
    asm volatile("ld.shared.b32 %0, [%1];" : "=r"(v) : "r"(a));
    return v;
}
__device__ __forceinline__ void sts16(uint32_t a, uint16_t v) {
    asm volatile("st.shared.u16 [%0], %1;" :: "r"(a), "h"(v));
}
// d[15:8] = e4m3(a), d[7:0] = e4m3(b)
__device__ __forceinline__ uint16_t cvt_e4m3x2(float a, float b) {
    uint16_t d;
    asm("cvt.rn.satfinite.e4m3x2.f32 %0, %1, %2;" : "=h"(d) : "f"(a), "f"(b));
    return d;
}
#define CP16(dst, src) \
    asm volatile("cp.async.cg.shared.global [%0], [%1], 16;" :: "r"(dst), "l"(src))
#define CP_COMMIT() asm volatile("cp.async.commit_group;" ::: "memory")
#define CP_WAIT0()  asm volatile("cp.async.wait_group 0;" ::: "memory")
#define CP_WAIT1()  asm volatile("cp.async.wait_group 1;" ::: "memory")

__device__ __forceinline__ uint32_t packh(float a, float b) {
    __half2 h = __floats2half2_rn(a, b);
    return *(uint32_t*)&h;
}
__device__ __forceinline__ float ex2(float s) {
    float p;
    asm("ex2.approx.f32 %0, %1;" : "=f"(p) : "f"(s));
    return p;
}

// ---------------------------------------------------------------------------
// cvt + csum partials
// ---------------------------------------------------------------------------
__global__ __launch_bounds__(256)
void cvtsum_kernel(const float* __restrict__ x) {
    const int t = threadIdx.x;
    const int sc = blockIdx.x, b = blockIdx.y;
    const float* xp = x + ((size_t)b * SEQ + (size_t)sc * 128) * DIM + 4 * t;
    __half* op = g_xh + ((size_t)b * SEQ + (size_t)sc * 128) * DIM + 4 * t;
    float s0 = 0.f, s1 = 0.f, s2 = 0.f, s3 = 0.f;
#pragma unroll 4
    for (int r = 0; r < 128; r++) {
        float4 v = *(const float4*)(xp + (size_t)r * DIM);
        s0 += v.x; s1 += v.y; s2 += v.z; s3 += v.w;
        *(uint2*)(op + (size_t)r * DIM) = make_uint2(packh(v.x, v.y), packh(v.z, v.w));
    }
    float* cp = g_cpart[sc] + b * DIM + 4 * t;
    cp[0] = s0; cp[1] = s1; cp[2] = s2; cp[3] = s3;
}
__global__ __launch_bounds__(256)
void csum2_kernel() {
    const int idx = blockIdx.x * 256 + threadIdx.x;
    float s = 0.f;
#pragma unroll
    for (int c = 0; c < 32; c++) s += g_cpart[c][idx];
    g_csum[idx] = s;
}

// ---------------------------------------------------------------------------
// qprep: Q -> g_Qt [64 n][1024 k] fp16, scaled by sqrt(log2 e)/32
// ---------------------------------------------------------------------------
__global__ __launch_bounds__(256)
void qprep_kernel(const float* __restrict__ Q) {
    __shared__ float ts[64][65];
    const int t = threadIdx.x;
    const int k0 = blockIdx.x * 64;
    const int r = t >> 2, cb = (t & 3) << 4;
    const float SC = 0.037535075274576556f;
    const float* qp = Q + (size_t)(k0 + r) * RNK + cb;
#pragma unroll
    for (int m = 0; m < 4; m++) {
        float4 v = *(const float4*)(qp + 4 * m);
        ts[r][cb + 4 * m + 0] = v.x * SC;
        ts[r][cb + 4 * m + 1] = v.y * SC;
        ts[r][cb + 4 * m + 2] = v.z * SC;
        ts[r][cb + 4 * m + 3] = v.w * SC;
    }
    __syncthreads();
    __half* o = g_Qt + (size_t)r * DIM + k0 + cb;
#pragma unroll
    for (int m = 0; m < 2; m++) {
        uint32_t w[4];
#pragma unroll
        for (int p = 0; p < 4; p++)
            w[p] = packh(ts[cb + 8 * m + 2 * p][r], ts[cb + 8 * m + 2 * p + 1][r]);
        *(uint4*)(o + 8 * m) = make_uint4(w[0], w[1], w[2], w[3]);
    }
}

// ---------------------------------------------------------------------------
// x8t: x fp32 [b][s][d] -> e4m3 [b][d][s]
// ---------------------------------------------------------------------------
__global__ __launch_bounds__(256)
void x8t_kernel(const float* __restrict__ x) {
    __shared__ float ts[64][65];
    const int t = threadIdx.x;
    const int s0 = blockIdx.x * 64, d0 = blockIdx.y * 64, b = blockIdx.z;
    const int r = t >> 2, cb = (t & 3) << 4;
    const float* xp = x + ((size_t)b * SEQ + s0 + r) * DIM + d0 + cb;
#pragma unroll
    for (int m = 0; m < 4; m++) {
        float4 v = *(const float4*)(xp + 4 * m);
        ts[r][cb + 4 * m + 0] = v.x; ts[r][cb + 4 * m + 1] = v.y;
        ts[r][cb + 4 * m + 2] = v.z; ts[r][cb + 4 * m + 3] = v.w;
    }
    __syncthreads();
    uint8_t* dst = g_x8t + ((size_t)b * DIM + d0 + r) * SEQ + s0 + cb;
    uint32_t w[4];
#pragma unroll
    for (int q = 0; q < 4; q++) {
        uint32_t lo = cvt_e4m3x2(ts[cb + 4 * q + 1][r], ts[cb + 4 * q + 0][r]);
        uint32_t hi = cvt_e4m3x2(ts[cb + 4 * q + 3][r], ts[cb + 4 * q + 2][r]);
        w[q] = lo | (hi << 16);
    }
    *(uint4*)dst = make_uint4(w[0], w[1], w[2], w[3]);
}

// ---------------------------------------------------------------------------
// ptrans: g_P [b][s][64] -> g_Pt [b][64][s]
// ---------------------------------------------------------------------------
__global__ __launch_bounds__(256)
void ptrans_kernel() {
    __shared__ uint16_t ts[64][68];
    const int t = threadIdx.x;
    const int s0 = blockIdx.x * 64, b = blockIdx.y;
    const int r = t >> 2, cb = (t & 3) << 4;
    const uint16_t* src = (const uint16_t*)g_P + ((size_t)b * SEQ + s0 + r) * RNK + cb;
#pragma unroll
    for (int m = 0; m < 4; m++)
        *(uint2*)&ts[r][cb + 4 * m] = *(const uint2*)(src + 4 * m);
    __syncthreads();
    uint32_t* dst = (uint32_t*)((uint16_t*)g_Pt + ((size_t)b * RNK + r) * SEQ + s0 + cb);
#pragma unroll
    for (int q = 0; q < 8; q++)
        dst[q] = (uint32_t)ts[cb + 2 * q][r] | ((uint32_t)ts[cb + 2 * q + 1][r] << 16);
}

// ---------------------------------------------------------------------------
// projH: P = x_h @ Qt^T via HMMA (unchanged)
// ---------------------------------------------------------------------------
#define POFF_X 0
#define POFF_Q 32768
#define PSM_TOTAL 49152

__global__ __launch_bounds__(256, 2)
void projH_kernel() {
    extern __shared__ char sm[];
    const uint32_t smb = smem_u32(sm);
    const int t = threadIdx.x;
    const int warp = t >> 5, lane = t & 31;
    const int row0 = blockIdx.x * 128;
    const int q0 = warp * 16;
    const int tg = lane & 3, g = lane >> 2;
    const int i7 = lane & 7, grp = lane >> 3;

    {
#pragma unroll
        for (int m = 0; m < 4; m++) {
            int idx = t + 256 * m;
            int row = idx >> 3, ch = idx & 7;
            uint32_t dsw = row * 128 + (((uint32_t)(ch ^ (row & 7))) << 4);
            CP16(smb + POFF_X + dsw, g_xh + (size_t)(row0 + row) * DIM + ch * 8);
        }
#pragma unroll
        for (int m = 0; m < 2; m++) {
            int idx = t + 256 * m;
            int row = idx >> 3, ch = idx & 7;
            uint32_t dsw = row * 128 + (((uint32_t)(ch ^ (row & 7))) << 4);
            CP16(smb + POFF_Q + dsw, g_Qt + (size_t)row * DIM + ch * 8);
        }
        CP_COMMIT();
    }

    const uint32_t rowA = q0 + i7 + ((grp & 1) << 3);
    const uint32_t cselA = grp >> 1;
    const uint32_t rowB = i7 + ((grp >> 1) << 3);
    const uint32_t cselB = grp & 1;

    float S[8][4];
#pragma unroll
    for (int n = 0; n < 8; n++)
#pragma unroll
        for (int e = 0; e < 4; e++) S[n][e] = 0.f;

    for (int c = 0; c < 16; c++) {
        const int buf = c & 1;
        CP_WAIT0();
        __syncthreads();
        if (c + 1 < 16) {
            const int kc = (c + 1) * 64;
            const int bo = buf ^ 1;
#pragma unroll
            for (int m = 0; m < 4; m++) {
                int idx = t + 256 * m;
                int row = idx >> 3, ch = idx & 7;
                uint32_t dsw = row * 128 + (((uint32_t)(ch ^ (row & 7))) << 4);
                CP16(smb + POFF_X + bo * 16384 + dsw,
                     g_xh + (size_t)(row0 + row) * DIM + kc + ch * 8);
            }
#pragma unroll
            for (int m = 0; m < 2; m++) {
                int idx = t + 256 * m;
                int row = idx >> 3, ch = idx & 7;
                uint32_t dsw = row * 128 + (((uint32_t)(ch ^ (row & 7))) << 4);
                CP16(smb + POFF_Q + bo * 8192 + dsw,
                     g_Qt + (size_t)row * DIM + kc + ch * 8);
            }
            CP_COMMIT();
        }
        const uint32_t xb = smb + POFF_X + buf * 16384;
        const uint32_t qb = smb + POFF_Q + buf * 8192;
#pragma unroll
        for (int kt = 0; kt < 4; kt++) {
            uint32_t ah[4];
            ldsm4(ah, xb + rowA * 128 + ((((kt << 1) + cselA) ^ i7) << 4));
#pragma unroll
            for (int np = 0; np < 4; np++) {
                uint32_t bh[4];
                ldsm4(bh, qb + ((np << 4) + rowB) * 128
                          + ((((kt << 1) + cselB) ^ i7) << 4));
                mma16816(S[2 * np],     ah, bh + 0);
                mma16816(S[2 * np + 1], ah, bh + 2);
            }
        }
        __syncthreads();
    }

    const int row = row0 + q0 + g;
#pragma unroll
    for (int j = 0; j < 8; j++) {
        const int nb = (j >> 1) * 16 + (j & 1) * 8;
        *(uint32_t*)&g_P[(size_t)row * RNK + nb + 2 * tg] = packh(S[j][0], S[j][1]);
        *(uint32_t*)&g_P[(size_t)(row + 8) * RNK + nb + 2 * tg] = packh(S[j][2], S[j][3]);
    }
}

// ---------------------------------------------------------------------------
// wproj: Wpart[kc] = Pt(64 r x 1024 k-slice) @ x_h(k x 256 d-slice), fp32 out
// grid (4 dsl, 8 b, 4 kc)
// ---------------------------------------------------------------------------
#define WOFF_P 0
#define WOFF_X 16384
#define WSM_TOTAL 81920

__global__ __launch_bounds__(256, 1)
void wproj_kernel() {
    extern __shared__ char sm[];
    const uint32_t smb = smem_u32(sm);
    const int t = threadIdx.x, warp = t >> 5, lane = t & 31;
    const int z = blockIdx.x, b = blockIdx.y, kc = blockIdx.z;
    const int i7 = lane & 7, grp = lane >> 3, tg = lane & 3, g = lane >> 2;
    const int w3 = warp & 3, h = warp >> 2;

    const __half* pt_g = g_Pt + (size_t)b * RNK * SEQ + (size_t)kc * 1024;
    const __half* x_g  = g_xh + ((size_t)b * SEQ + (size_t)kc * 1024) * DIM + z * 256;

    // prefetch iter 0
    {
#pragma unroll
        for (int m = 0; m < 2; m++) {
            int idx = t + 256 * m;
            int row = idx >> 3, ch = idx & 7;
            uint32_t dsw = row * 128 + (((uint32_t)(ch ^ (row & 7))) << 4);
            CP16(smb + WOFF_P + dsw, pt_g + (size_t)row * SEQ + ch * 8);
        }
#pragma unroll
        for (int m = 0; m < 8; m++) {
            int idx = t + 256 * m;
            int row = idx >> 5, ch = idx & 31;
            uint32_t dsw = row * 512 + (((uint32_t)(ch ^ (row & 7))) << 4);
            CP16(smb + WOFF_X + dsw, x_g + (size_t)row * DIM + ch * 8);
        }
        CP_COMMIT();
    }

    const uint32_t rowA = 16 * w3 + i7 + ((grp & 1) << 3);
    const uint32_t cselA = grp >> 1;
    const uint32_t rowV = i7 + ((grp & 1) << 3);
    const uint32_t cselV = grp >> 1;

    float W[16][4];
#pragma unroll
    for (int n = 0; n < 16; n++)
#pragma unroll
        for (int e = 0; e < 4; e++) W[n][e] = 0.f;

    for (int it = 0; it < 16; it++) {
        const int buf = it & 1;
        CP_WAIT0();
        __syncthreads();
        if (it + 1 < 16) {
            const int kk = (it + 1) * 64;
            const int bo = buf ^ 1;
#pragma unroll
            for (int m = 0; m < 2; m++) {
                int idx = t + 256 * m;
                int row = idx >> 3, ch = idx & 7;
                uint32_t dsw = row * 128 + (((uint32_t)(ch ^ (row & 7))) << 4);
                CP16(smb + WOFF_P + bo * 8192 + dsw,
                     pt_g + (size_t)row * SEQ + kk + ch * 8);
            }
#pragma unroll
            for (int m = 0; m < 8; m++) {
                int idx = t + 256 * m;
                int row = idx >> 5, ch = idx & 31;
                uint32_t dsw = row * 512 + (((uint32_t)(ch ^ (row & 7))) << 4);
                CP16(smb + WOFF_X + bo * 32768 + dsw,
                     x_g + (size_t)(kk + row) * DIM + ch * 8);
            }
            CP_COMMIT();
        }
        const uint32_t pB = smb + WOFF_P + buf * 8192;
        const uint32_t xB = smb + WOFF_X + buf * 32768;
#pragma unroll
        for (int kt = 0; kt < 4; kt++) {
            uint32_t a[4];
            ldsm4(a, pB + rowA * 128 + ((((kt << 1) + cselA) ^ i7) << 4));
#pragma unroll
            for (int np = 0; np < 8; np++) {
                uint32_t bh[4];
                ldsm4t(bh, xB + ((kt << 4) + rowV) * 512
                           + ((((h << 4) + (np << 1) + cselV) ^ i7) << 4));
                mma16816(W[2 * np],     a, bh + 0);
                mma16816(W[2 * np + 1], a, bh + 2);
            }
        }
        __syncthreads();
    }

    float* wp = g_Wpart[kc] + (size_t)b * RNK * DIM + (size_t)z * 256;
#pragma unroll
    for (int np = 0; np < 16; np++) {
        const int d = h * 128 + np * 8 + 2 * tg;
        const int r = 16 * w3 + g;
        float2 v0 = make_float2(W[np][0], W[np][1]);
        float2 v1 = make_float2(W[np][2], W[np][3]);
        *(float2*)(wp + (size_t)r * DIM + d) = v0;
        *(float2*)(wp + (size_t)(r + 8) * DIM + d) = v1;
    }
}
__global__ __launch_bounds__(256)
void wred_kernel() {
    const int idx = blockIdx.x * 256 + threadIdx.x;
    float s = ((g_Wpart[0][idx] + g_Wpart[1][idx]) + g_Wpart[2][idx]) + g_Wpart[3][idx];
    g_W[idx] = __float2half_rn(s * 22.18070977791825f);   // 32*ln2
}

// ---------------------------------------------------------------------------
// attn: fp16 QK + fp8 residual PV + rank-64 first-order prologue.
// smem: PQ 16K | PK 2x16K | W 32K | panel 10K | V8 2x36864
// ---------------------------------------------------------------------------
#define OFF_PQ   0
#define OFF_PK   16384
#define OFF_W    49152
#define OFF_PAN  81920
#define OFF_V8   92160
#define VBUF     36864
#define SMEM_TOTAL 165888

__global__ __launch_bounds__(256, 1)
void attn_kernel(float* __restrict__ out) {
    extern __shared__ char sm[];
    const uint32_t smb = smem_u32(sm);
    const int t = threadIdx.x;
    const int warp = t >> 5, lane = t & 31;
    const int qb = blockIdx.x, z = blockIdx.y, b = blockIdx.z;
    const int q0 = warp * 16;
    const int tg = lane & 3, g = lane >> 2;
    const int i7 = lane & 7, grp = lane >> 3;

    const __half* pk_g = g_P + (size_t)b * SEQ * RNK;
    const uint8_t* x8_g = g_x8t + ((size_t)b * DIM + (size_t)z * 256) * SEQ;

    // ---- PQ direct load ----
#pragma unroll
    for (int m = 0; m < 4; m++) {
        int idx = t + 256 * m;
        int row = idx >> 3, ch = idx & 7;
        size_t src = ((size_t)b * SEQ + (size_t)qb * 128 + row) * RNK + ch * 8;
        uint32_t dst = row * 128 + (((uint32_t)(ch ^ (row & 7))) << 4);
        *(uint4*)(sm + OFF_PQ + dst) = *(const uint4*)(g_P + src);
    }
    // ---- cp W tile (group 0) ----
#pragma unroll
    for (int m = 0; m < 8; m++) {
        int idx = t + 256 * m;
        int row = idx >> 5, ch = idx & 31;
        uint32_t dsw = OFF_W + row * 512 + (((uint32_t)(ch ^ (row & 7))) << 4);
        CP16(smb + dsw, g_W + (size_t)b * RNK * DIM + (size_t)row * DIM + z * 256 + ch * 8);
    }
    CP_COMMIT();
    // ---- cp tile 0 (group 1) ----
    {
#pragma unroll
        for (int m = 0; m < 4; m++) {
            int idx = t + 256 * m;
            int row = idx >> 3, ch = idx & 7;
            uint32_t dsw = row * 128 + (((uint32_t)(ch ^ (row & 7))) << 4);
            CP16(smb + OFF_PK + dsw, pk_g + (size_t)row * RNK + ch * 8);
        }
#pragma unroll
        for (int m = 0; m < 8; m++) {
            int idx = t + 256 * m;
            int d = idx >> 3, c = idx & 7;
            CP16(smb + OFF_V8 + d * 144 + c * 16, x8_g + (size_t)d * SEQ + c * 16);
        }
        CP_COMMIT();
    }
    __syncthreads();

    // ---- hoist Pq A-frags ----
    const uint32_t rowA = q0 + i7 + ((grp & 1) << 3);
    const uint32_t cselA = grp >> 1;
    uint32_t aReg[4][4];
#pragma unroll
    for (int kt = 0; kt < 4; kt++)
        ldsm4(aReg[kt], smb + OFF_PQ + rowA * 128 + ((((kt << 1) + cselA) ^ i7) << 4));

    float Y[32][4];
#pragma unroll
    for (int n = 0; n < 32; n++)
#pragma unroll
        for (int e = 0; e < 4; e++) Y[n][e] = 0.f;
    float rl = 0.f, rh = 0.f;

    const uint32_t rowB = i7 + ((grp >> 1) << 3);
    const uint32_t cselB = grp & 1;
    const uint32_t rowV = i7 + ((grp & 1) << 3);
    const uint32_t cselV = grp >> 1;

    // ---- first-order: Y = Pq @ W ----
    CP_WAIT1();
    __syncthreads();
    {
        const uint32_t wB = smb + OFF_W;
#pragma unroll
        for (int kt = 0; kt < 4; kt++) {
            uint32_t vrow = wB + ((kt << 4) + rowV) * 512;
#pragma unroll
            for (int np = 0; np < 16; np++) {
                uint32_t bh[4];
                ldsm4t(bh, vrow + ((((np << 1) + cselV) ^ i7) << 4));
                mma16816(Y[2 * np],     aReg[kt], bh + 0);
                mma16816(Y[2 * np + 1], aReg[kt], bh + 2);
            }
        }
    }

    const uint32_t panB = smb + OFF_PAN + warp * 1280;
    const uint32_t vLane = ((lane & 7) + ((lane >> 4) << 3)) * 144 + (((lane >> 3) & 1) << 4);
    const float LN2_32 = 22.18070977791825f;

    for (int it = 0; it < NIT; it++) {
        const int buf = it & 1;
        CP_WAIT0();
        __syncthreads();

        if (it + 1 < NIT) {
            const int k0n = (it + 1) * KB;
            const int bo = buf ^ 1;
#pragma unroll
            for (int m = 0; m < 4; m++) {
                int idx = t + 256 * m;
                int row = idx >> 3, ch = idx & 7;
                uint32_t dsw = row * 128 + (((uint32_t)(ch ^ (row & 7))) << 4);
                CP16(smb + OFF_PK + bo * 16384 + dsw,
                     pk_g + (size_t)(k0n + row) * RNK + ch * 8);
            }
#pragma unroll
            for (int m = 0; m < 8; m++) {
                int idx = t + 256 * m;
                int d = idx >> 3, c = idx & 7;
                CP16(smb + OFF_V8 + bo * VBUF + d * 144 + c * 16,
                     x8_g + (size_t)d * SEQ + k0n + c * 16);
            }
            CP_COMMIT();
        }

#pragma unroll
        for (int sub = 0; sub < 2; sub++) {
            const uint32_t pkBase = smb + OFF_PK + buf * 16384 + sub * 8192;
            const uint32_t vSub   = smb + OFF_V8 + buf * VBUF + sub * 64 + vLane;

            // QK^T
            float S[8][4];
#pragma unroll
            for (int n = 0; n < 8; n++)
#pragma unroll
                for (int e = 0; e < 4; e++) S[n][e] = 0.f;
#pragma unroll
            for (int kt = 0; kt < 4; kt++) {
#pragma unroll
                for (int np = 0; np < 4; np++) {
                    uint32_t bh[4];
                    ldsm4(bh, pkBase + ((np << 4) + rowB) * 128
                              + ((((kt << 1) + cselB) ^ i7) << 4));
                    mma16816(S[2 * np],     aReg[kt], bh + 0);
                    mma16816(S[2 * np + 1], aReg[kt], bh + 2);
                }
            }

            // softmax -> residual g*32 -> panel
            __syncwarp();
#pragma unroll
            for (int n = 0; n < 8; n++) {
                float t0 = S[n][0], t1 = S[n][1], t2 = S[n][2], t3 = S[n][3];
                float p0 = ex2(t0), p1 = ex2(t1), p2 = ex2(t2), p3 = ex2(t3);
                rl += p0 + p1;
                rh += p2 + p3;
                float g0 = fmaf(t0, -LN2_32, fmaf(p0, 32.f, -32.f));
                float g1 = fmaf(t1, -LN2_32, fmaf(p1, 32.f, -32.f));
                float g2 = fmaf(t2, -LN2_32, fmaf(p2, 32.f, -32.f));
                float g3 = fmaf(t3, -LN2_32, fmaf(p3, 32.f, -32.f));
                uint32_t kcol = ((n >> 1) << 4) + ((n & 1) << 3) + 2 * tg;
                sts16(panB + g * 80 + kcol, cvt_e4m3x2(g1, g0));
                sts16(panB + (g + 8) * 80 + kcol, cvt_e4m3x2(g3, g2));
            }
            __syncwarp();

            // PV fp8
#pragma unroll
            for (int kt8 = 0; kt8 < 2; kt8++) {
                const uint32_t k0b = kt8 * 32;
                uint32_t aF[4];
                aF[0] = lds32(panB + g * 80 + k0b + 4 * tg);
                aF[1] = lds32(panB + (g + 8) * 80 + k0b + 4 * tg);
                aF[2] = lds32(panB + g * 80 + k0b + 16 + 4 * tg);
                aF[3] = lds32(panB + (g + 8) * 80 + k0b + 16 + 4 * tg);
#pragma unroll
                for (int dnp = 0; dnp < 16; dnp++) {
                    uint32_t bh[4];
                    ldsm4(bh, vSub + dnp * 2304 + k0b);
                    mma_f8(Y[2 * dnp],     aF, bh[0], bh[1]);
                    mma_f8(Y[2 * dnp + 1], aF, bh[2], bh[3]);
                }
            }
        }
    }

    rl += __shfl_xor_sync(0xffffffffu, rl, 1);
    rl += __shfl_xor_sync(0xffffffffu, rl, 2);
    rh += __shfl_xor_sync(0xffffffffu, rh, 1);
    rh += __shfl_xor_sync(0xffffffffu, rh, 2);

    const float il = 1.0f / rl;
    const float ih = 1.0f / rh;
    const int rlo = qb * 128 + q0 + g;
    const float* cs_base = g_csum + b * DIM + z * 256 + 2 * tg;
    float* o_lo = out + ((size_t)b * SEQ + rlo) * DIM + (size_t)z * 256 + 2 * tg;
    float* o_hi = o_lo + (size_t)8 * DIM;
#pragma unroll
    for (int n = 0; n < 32; n++) {
        float2 cs = *(const float2*)(cs_base + 8 * n);
        float2 p;
        p.x = fmaf(Y[n][0], 0.03125f, cs.x) * il;
        p.y = fmaf(Y[n][1], 0.03125f, cs.y) * il;
        *(float2*)(o_lo + 8 * n) = p;
        p.x = fmaf(Y[n][2], 0.03125f, cs.x) * ih;
        p.y = fmaf(Y[n][3], 0.03125f, cs.y) * ih;
        *(float2*)(o_hi + 8 * n) = p;
    }
}

// ---------------------------------------------------------------------------
extern "C" void kernel_launch(void* const* d_in, const int* in_sizes, int n_in,
                              void* d_out, int out_size) {
    const float* x = (const float*)d_in[0];
    const float* Q = (const float*)d_in[1];
    float* out = (float*)d_out;

    cudaFuncSetAttribute(attn_kernel, cudaFuncAttributeMaxDynamicSharedMemorySize,
                         SMEM_TOTAL);
    cudaFuncSetAttribute(projH_kernel, cudaFuncAttributeMaxDynamicSharedMemorySize,
                         PSM_TOTAL);
    cudaFuncSetAttribute(wproj_kernel, cudaFuncAttributeMaxDynamicSharedMemorySize,
                         WSM_TOTAL);

    cvtsum_kernel<<<dim3(SEQ / 128, BATCH), 256>>>(x);
    qprep_kernel<<<DIM / 64, 256>>>(Q);
    x8t_kernel<<<dim3(SEQ / 64, DIM / 64, BATCH), 256>>>(x);
    projH_kernel<<<BATCH * SEQ / 128, 256, PSM_TOTAL>>>();
    ptrans_kernel<<<dim3(SEQ / 64, BATCH), 256>>>();
    csum2_kernel<<<BATCH * DIM / 256, 256>>>();
    wproj_kernel<<<dim3(4, BATCH, 4), 256, WSM_TOTAL>>>();
    wred_kernel<<<BATCH * RNK * DIM / 256, 256>>>();
    attn_kernel<<<dim3(SEQ / 128, DIM / 256, BATCH), 256, SMEM_TOTAL>>>(out);
}

// round 12
// speedup vs baseline: 1.1174x; 1.1174x over previous
#include <cuda_runtime.h>
#include <cuda_fp16.h>
#include <cstdint>

#define BATCH 8
#define SEQ   4096
#define DIM   1024
#define RNK   64
#define KB    128
#define NIT   (SEQ/KB)

// ---------------- global scratch ----------------
__device__ __align__(16) __half g_P[BATCH * SEQ * RNK];
__device__ __align__(16) __half g_xh[(size_t)BATCH * SEQ * DIM];
__device__ __align__(16) __half g_Qt[RNK * DIM];          // Q^T * sqrt(log2e)/32, fp16
__device__ __align__(16) float  g_csum[BATCH * DIM];
__device__ __align__(16) float  g_cpart[32][BATCH * DIM];

// ---------------- helpers ----------------
__device__ __forceinline__ uint32_t smem_u32(const void* p) {
    uint32_t a;
    asm("{ .reg .u64 t; cvta.to.shared.u64 t, %1; cvt.u32.u64 %0, t; }" : "=r"(a) : "l"(p));
    return a;
}
__device__ __forceinline__ void ldsm4(uint32_t* r, uint32_t a) {
    asm volatile("ldmatrix.sync.aligned.m8n8.x4.shared.b16 {%0,%1,%2,%3}, [%4];"
        : "=r"(r[0]), "=r"(r[1]), "=r"(r[2]), "=r"(r[3]) : "r"(a));
}
__device__ __forceinline__ void ldsm4t(uint32_t* r, uint32_t a) {
    asm volatile("ldmatrix.sync.aligned.m8n8.x4.trans.shared.b16 {%0,%1,%2,%3}, [%4];"
        : "=r"(r[0]), "=r"(r[1]), "=r"(r[2]), "=r"(r[3]) : "r"(a));
}
__device__ __forceinline__ void mma16816(float* d, const uint32_t* a, const uint32_t* b) {
    asm volatile(
        "mma.sync.aligned.m16n8k16.row.col.f32.f16.f16.f32 "
        "{%0,%1,%2,%3}, {%4,%5,%6,%7}, {%8,%9}, {%0,%1,%2,%3};"
        : "+f"(d[0]), "+f"(d[1]), "+f"(d[2]), "+f"(d[3])
        : "r"(a[0]), "r"(a[1]), "r"(a[2]), "r"(a[3]), "r"(b[0]), "r"(b[1]));
}
#define CP16(dst, src) \
    asm volatile("cp.async.cg.shared.global [%0], [%1], 16;" :: "r"(dst), "l"(src))
#define CP_COMMIT() asm volatile("cp.async.commit_group;" ::: "memory")
#define CP_WAIT0()  asm volatile("cp.async.wait_group 0;" ::: "memory")

__device__ __forceinline__ uint32_t packh(float a, float b) {
    __half2 h = __floats2half2_rn(a, b);
    return *(uint32_t*)&h;
}
// exp with log2e pre-folded into the logits: p = 2^s (single MUFU op)
__device__ __forceinline__ float ex2(float s) {
    float p;
    asm("ex2.approx.f32 %0, %1;" : "=f"(p) : "f"(s));
    return p;
}

// ---------------------------------------------------------------------------
// Fused cvt + csum: x fp32 -> fp16, and per-128-row-chunk column sums.
// ---------------------------------------------------------------------------
__global__ __launch_bounds__(256)
void cvtsum_kernel(const float* __restrict__ x) {
    const int t = threadIdx.x;
    const int sc = blockIdx.x, b = blockIdx.y;
    const float* xp = x + ((size_t)b * SEQ + (size_t)sc * 128) * DIM + 4 * t;
    __half* op = g_xh + ((size_t)b * SEQ + (size_t)sc * 128) * DIM + 4 * t;
    float s0 = 0.f, s1 = 0.f, s2 = 0.f, s3 = 0.f;
#pragma unroll 4
    for (int r = 0; r < 128; r++) {
        float4 v = *(const float4*)(xp + (size_t)r * DIM);
        s0 += v.x; s1 += v.y; s2 += v.z; s3 += v.w;
        *(uint2*)(op + (size_t)r * DIM) = make_uint2(packh(v.x, v.y), packh(v.z, v.w));
    }
    float* cp = g_cpart[sc] + b * DIM + 4 * t;
    cp[0] = s0; cp[1] = s1; cp[2] = s2; cp[3] = s3;
}
__global__ __launch_bounds__(256)
void csum2_kernel() {
    const int idx = blockIdx.x * 256 + threadIdx.x;
    float s = 0.f;
#pragma unroll
    for (int c = 0; c < 32; c++) s += g_cpart[c][idx];
    g_csum[idx] = s;
}

// ---------------------------------------------------------------------------
// qprep: Q -> g_Qt [64 n][1024 k] fp16, scaled by sqrt(log2 e)/32
// ---------------------------------------------------------------------------
__global__ __launch_bounds__(256)
void qprep_kernel(const float* __restrict__ Q) {
    __shared__ float ts[64][65];
    const int t = threadIdx.x;
    const int k0 = blockIdx.x * 64;
    const int r = t >> 2, cb = (t & 3) << 4;
    const float SC = 0.037535075274576556f;   // sqrt(log2 e) / 32
    const float* qp = Q + (size_t)(k0 + r) * RNK + cb;
#pragma unroll
    for (int m = 0; m < 4; m++) {
        float4 v = *(const float4*)(qp + 4 * m);
        ts[r][cb + 4 * m + 0] = v.x * SC;
        ts[r][cb + 4 * m + 1] = v.y * SC;
        ts[r][cb + 4 * m + 2] = v.z * SC;
        ts[r][cb + 4 * m + 3] = v.w * SC;
    }
    __syncthreads();
    __half* o = g_Qt + (size_t)r * DIM + k0 + cb;
#pragma unroll
    for (int m = 0; m < 2; m++) {
        uint32_t w[4];
#pragma unroll
        for (int p = 0; p < 4; p++)
            w[p] = packh(ts[cb + 8 * m + 2 * p][r], ts[cb + 8 * m + 2 * p + 1][r]);
        *(uint4*)(o + 8 * m) = make_uint4(w[0], w[1], w[2], w[3]);
    }
}

// ---------------------------------------------------------------------------
// projH: P = x_h @ Qt^T via HMMA
// ---------------------------------------------------------------------------
#define POFF_X 0
#define POFF_Q 32768
#define PSM_TOTAL 49152

__global__ __launch_bounds__(256, 2)
void projH_kernel() {
    extern __shared__ char sm[];
    const uint32_t smb = smem_u32(sm);
    const int t = threadIdx.x;
    const int warp = t >> 5, lane = t & 31;
    const int row0 = blockIdx.x * 128;
    const int q0 = warp * 16;
    const int tg = lane & 3, g = lane >> 2;
    const int i7 = lane & 7, grp = lane >> 3;

    {
#pragma unroll
        for (int m = 0; m < 4; m++) {
            int idx = t + 256 * m;
            int row = idx >> 3, ch = idx & 7;
            uint32_t dsw = row * 128 + (((uint32_t)(ch ^ (row & 7))) << 4);
            CP16(smb + POFF_X + dsw, g_xh + (size_t)(row0 + row) * DIM + ch * 8);
        }
#pragma unroll
        for (int m = 0; m < 2; m++) {
            int idx = t + 256 * m;
            int row = idx >> 3, ch = idx & 7;
            uint32_t dsw = row * 128 + (((uint32_t)(ch ^ (row & 7))) << 4);
            CP16(smb + POFF_Q + dsw, g_Qt + (size_t)row * DIM + ch * 8);
        }
        CP_COMMIT();
    }

    const uint32_t rowA = q0 + i7 + ((grp & 1) << 3);
    const uint32_t cselA = grp >> 1;
    const uint32_t rowB = i7 + ((grp >> 1) << 3);
    const uint32_t cselB = grp & 1;

    float S[8][4];
#pragma unroll
    for (int n = 0; n < 8; n++)
#pragma unroll
        for (int e = 0; e < 4; e++) S[n][e] = 0.f;

    for (int c = 0; c < 16; c++) {
        const int buf = c & 1;
        CP_WAIT0();
        __syncthreads();
        if (c + 1 < 16) {
            const int kc = (c + 1) * 64;
            const int bo = buf ^ 1;
#pragma unroll
            for (int m = 0; m < 4; m++) {
                int idx = t + 256 * m;
                int row = idx >> 3, ch = idx & 7;
                uint32_t dsw = row * 128 + (((uint32_t)(ch ^ (row & 7))) << 4);
                CP16(smb + POFF_X + bo * 16384 + dsw,
                     g_xh + (size_t)(row0 + row) * DIM + kc + ch * 8);
            }
#pragma unroll
            for (int m = 0; m < 2; m++) {
                int idx = t + 256 * m;
                int row = idx >> 3, ch = idx & 7;
                uint32_t dsw = row * 128 + (((uint32_t)(ch ^ (row & 7))) << 4);
                CP16(smb + POFF_Q + bo * 8192 + dsw,
                     g_Qt + (size_t)row * DIM + kc + ch * 8);
            }
            CP_COMMIT();
        }
        const uint32_t xb = smb + POFF_X + buf * 16384;
        const uint32_t qb = smb + POFF_Q + buf * 8192;
#pragma unroll
        for (int kt = 0; kt < 4; kt++) {
            uint32_t ah[4];
            ldsm4(ah, xb + rowA * 128 + ((((kt << 1) + cselA) ^ i7) << 4));
#pragma unroll
            for (int np = 0; np < 4; np++) {
                uint32_t bh[4];
                ldsm4(bh, qb + ((np << 4) + rowB) * 128
                          + ((((kt << 1) + cselB) ^ i7) << 4));
                mma16816(S[2 * np],     ah, bh + 0);
                mma16816(S[2 * np + 1], ah, bh + 2);
            }
        }
        __syncthreads();
    }

    const int row = row0 + q0 + g;
#pragma unroll
    for (int j = 0; j < 8; j++) {
        const int nb = (j >> 1) * 16 + (j & 1) * 8;
        *(uint32_t*)&g_P[(size_t)row * RNK + nb + 2 * tg] = packh(S[j][0], S[j][1]);
        *(uint32_t*)&g_P[(size_t)(row + 8) * RNK + nb + 2 * tg] = packh(S[j][2], S[j][3]);
    }
}

// ---------------------------------------------------------------------------
// Flash attention, fp16 HMMA, KB=128 buffers, warp tile = 32q x 128d
// (one V fragment feeds two q-halves => V smem reads halved).
// grid (32 qtiles, 4 d-slices, 8 batches), 256 threads.
// smem: PQ 16K | PK 2x16K | V 2x64K = 176K
// ---------------------------------------------------------------------------
#define OFF_PQ   0
#define OFF_PK   16384
#define OFF_V    49152
#define SMEM_TOTAL 180224

__global__ __launch_bounds__(256, 1)
void attn_kernel(float* __restrict__ out) {
    extern __shared__ char sm[];
    const uint32_t smb = smem_u32(sm);
    const int t = threadIdx.x;
    const int warp = t >> 5, lane = t & 31;
    const int qb = blockIdx.x, z = blockIdx.y, b = blockIdx.z;
    const int qw = warp & 3, dh = warp >> 2;       // q-group (32 rows), d-half (128)
    const int q0 = qw * 32;
    const int tg = lane & 3, g = lane >> 2;
    const int i7 = lane & 7, grp = lane >> 3;

    const __half* pk_g = g_P + (size_t)b * SEQ * RNK;
    const __half* vh_g = g_xh + (size_t)b * SEQ * DIM + (size_t)z * 256;

    // ---- load Pq tile [128 q][64 r] into smem (swizzled) ----
#pragma unroll
    for (int m = 0; m < 4; m++) {
        int idx = t + 256 * m;
        int row = idx >> 3, ch = idx & 7;
        size_t src = ((size_t)b * SEQ + (size_t)qb * 128 + row) * RNK + ch * 8;
        uint32_t dst = row * 128 + (((uint32_t)(ch ^ (row & 7))) << 4);
        *(uint4*)(sm + OFF_PQ + dst) = *(const uint4*)(g_P + src);
    }
    // ---- prefetch tile 0 (128 keys) ----
    {
#pragma unroll
        for (int m = 0; m < 4; m++) {
            int idx = t + 256 * m;
            int row = idx >> 3, ch = idx & 7;
            uint32_t dsw = row * 128 + (((uint32_t)(ch ^ (row & 7))) << 4);
            CP16(smb + OFF_PK + dsw, pk_g + (size_t)row * RNK + ch * 8);
        }
#pragma unroll
        for (int m = 0; m < 16; m++) {
            int idx = t + 256 * m;
            int row = idx >> 5, ch = idx & 31;
            uint32_t dsw = row * 512 + (((uint32_t)(ch ^ (row & 7))) << 4);
            CP16(smb + OFF_V + dsw, vh_g + (size_t)row * DIM + ch * 8);
        }
        CP_COMMIT();
    }
    __syncthreads();

    float Y0[16][4], Y1[16][4];
#pragma unroll
    for (int n = 0; n < 16; n++)
#pragma unroll
        for (int e = 0; e < 4; e++) { Y0[n][e] = 0.f; Y1[n][e] = 0.f; }
    float rs[4] = {0.f, 0.f, 0.f, 0.f};   // rl0, rh0, rl1, rh1

    const uint32_t cselA = grp >> 1;
    const uint32_t rowB = i7 + ((grp >> 1) << 3);
    const uint32_t cselB = grp & 1;
    const uint32_t rowV = i7 + ((grp & 1) << 3);
    const uint32_t cselV = grp >> 1;
    const uint32_t rowA0 = q0 + i7 + ((grp & 1) << 3);

    for (int it = 0; it < NIT; it++) {
        const int buf = it & 1;
        CP_WAIT0();
        __syncthreads();

        // prefetch tile it+1 (overlaps compute)
        if (it + 1 < NIT) {
            const int k0n = (it + 1) * KB;
            const int bo = buf ^ 1;
#pragma unroll
            for (int m = 0; m < 4; m++) {
                int idx = t + 256 * m;
                int row = idx >> 3, ch = idx & 7;
                uint32_t dsw = row * 128 + (((uint32_t)(ch ^ (row & 7))) << 4);
                CP16(smb + OFF_PK + bo * 16384 + dsw,
                     pk_g + (size_t)(k0n + row) * RNK + ch * 8);
            }
#pragma unroll
            for (int m = 0; m < 16; m++) {
                int idx = t + 256 * m;
                int row = idx >> 5, ch = idx & 31;
                uint32_t dsw = row * 512 + (((uint32_t)(ch ^ (row & 7))) << 4);
                CP16(smb + OFF_V + bo * 65536 + dsw,
                     vh_g + (size_t)(k0n + row) * DIM + ch * 8);
            }
            CP_COMMIT();
        }

        // ---- two 64-key subtiles within the buffer ----
#pragma unroll
        for (int sub = 0; sub < 2; sub++) {
            const uint32_t pkBase = smb + OFF_PK + buf * 16384 + sub * 8192;
            const uint32_t vBase  = smb + OFF_V  + buf * 65536 + sub * 32768;

            uint32_t Ph[2][4][4];
            // --- per 16q half: QK + softmax ---
#pragma unroll
            for (int hf = 0; hf < 2; hf++) {
                float S[8][4];
#pragma unroll
                for (int n = 0; n < 8; n++)
#pragma unroll
                    for (int e = 0; e < 4; e++) S[n][e] = 0.f;
                const uint32_t rowA = rowA0 + hf * 16;
#pragma unroll
                for (int kt = 0; kt < 4; kt++) {
                    uint32_t ah[4];
                    ldsm4(ah, smb + OFF_PQ + rowA * 128
                              + ((((kt << 1) + cselA) ^ i7) << 4));
#pragma unroll
                    for (int np = 0; np < 4; np++) {
                        uint32_t bh[4];
                        ldsm4(bh, pkBase + ((np << 4) + rowB) * 128
                                  + ((((kt << 1) + cselB) ^ i7) << 4));
                        mma16816(S[2 * np],     ah, bh + 0);
                        mma16816(S[2 * np + 1], ah, bh + 2);
                    }
                }
                float rl = 0.f, rh = 0.f;
#pragma unroll
                for (int n = 0; n < 8; n++) {
                    S[n][0] = ex2(S[n][0]);
                    S[n][1] = ex2(S[n][1]);
                    S[n][2] = ex2(S[n][2]);
                    S[n][3] = ex2(S[n][3]);
                    rl += S[n][0] + S[n][1];
                    rh += S[n][2] + S[n][3];
                }
                rs[2 * hf] += rl;
                rs[2 * hf + 1] += rh;
#pragma unroll
                for (int kt = 0; kt < 4; kt++) {
                    const int n0 = 2 * kt;
                    Ph[hf][kt][0] = packh(S[n0][0] - 1.f,     S[n0][1] - 1.f);
                    Ph[hf][kt][1] = packh(S[n0][2] - 1.f,     S[n0][3] - 1.f);
                    Ph[hf][kt][2] = packh(S[n0 + 1][0] - 1.f, S[n0 + 1][1] - 1.f);
                    Ph[hf][kt][3] = packh(S[n0 + 1][2] - 1.f, S[n0 + 1][3] - 1.f);
                }
            }

            // --- joint PV: each V fragment feeds both q-halves ---
#pragma unroll
            for (int kt = 0; kt < 4; kt++) {
                uint32_t vrow = vBase + ((kt << 4) + rowV) * 512;
#pragma unroll
                for (int np = 0; np < 8; np++) {
                    uint32_t bh[4];
                    ldsm4t(bh, vrow + ((((dh << 4) + (np << 1) + cselV) ^ i7) << 4));
                    mma16816(Y0[2 * np],     Ph[0][kt], bh + 0);
                    mma16816(Y0[2 * np + 1], Ph[0][kt], bh + 2);
                    mma16816(Y1[2 * np],     Ph[1][kt], bh + 0);
                    mma16816(Y1[2 * np + 1], Ph[1][kt], bh + 2);
                }
            }
        }
    }

    // ---- row-sum reductions ----
#pragma unroll
    for (int i = 0; i < 4; i++) {
        rs[i] += __shfl_xor_sync(0xffffffffu, rs[i], 1);
        rs[i] += __shfl_xor_sync(0xffffffffu, rs[i], 2);
    }

    // ---- epilogue: y = (csum + Ydot) / l ----
    const float il0 = 1.0f / rs[0], ih0 = 1.0f / rs[1];
    const float il1 = 1.0f / rs[2], ih1 = 1.0f / rs[3];
    const int rbase = qb * 128 + q0 + g;
    const float* cs_base = g_csum + b * DIM + z * 256 + dh * 128 + 2 * tg;
    float* o0 = out + ((size_t)b * SEQ + rbase) * DIM + (size_t)z * 256 + dh * 128 + 2 * tg;
    float* o1 = o0 + (size_t)8 * DIM;     // +8 rows
    float* o2 = o0 + (size_t)16 * DIM;    // +16 rows
    float* o3 = o0 + (size_t)24 * DIM;    // +24 rows
#pragma unroll
    for (int n = 0; n < 16; n++) {
        float2 cs = *(const float2*)(cs_base + 8 * n);
        float2 p;
        p.x = (Y0[n][0] + cs.x) * il0; p.y = (Y0[n][1] + cs.y) * il0;
        *(float2*)(o0 + 8 * n) = p;
        p.x = (Y0[n][2] + cs.x) * ih0; p.y = (Y0[n][3] + cs.y) * ih0;
        *(float2*)(o1 + 8 * n) = p;
        p.x = (Y1[n][0] + cs.x) * il1; p.y = (Y1[n][1] + cs.y) * il1;
        *(float2*)(o2 + 8 * n) = p;
        p.x = (Y1[n][2] + cs.x) * ih1; p.y = (Y1[n][3] + cs.y) * ih1;
        *(float2*)(o3 + 8 * n) = p;
    }
}

// ---------------------------------------------------------------------------
extern "C" void kernel_launch(void* const* d_in, const int* in_sizes, int n_in,
                              void* d_out, int out_size) {
    const float* x = (const float*)d_in[0];
    const float* Q = (const float*)d_in[1];
    float* out = (float*)d_out;

    cudaFuncSetAttribute(attn_kernel, cudaFuncAttributeMaxDynamicSharedMemorySize,
                         SMEM_TOTAL);
    cudaFuncSetAttribute(projH_kernel, cudaFuncAttributeMaxDynamicSharedMemorySize,
                         PSM_TOTAL);

    cvtsum_kernel<<<dim3(SEQ / 128, BATCH), 256>>>(x);
    qprep_kernel<<<DIM / 64, 256>>>(Q);
    projH_kernel<<<BATCH * SEQ / 128, 256, PSM_TOTAL>>>();
    csum2_kernel<<<BATCH * DIM / 256, 256>>>();
    attn_kernel<<<dim3(SEQ / 128, DIM / 256, BATCH), 256, SMEM_TOTAL>>>(out);
}

// round 13
// speedup vs baseline: 1.3518x; 1.2098x over previous
#include <cuda_runtime.h>
#include <cuda_fp16.h>
#include <cstdint>

#define BATCH 8
#define SEQ   4096
#define DIM   1024
#define RNK   64
#define KB    128
#define NIT   (SEQ/KB)

// ---------------- global scratch ----------------
__device__ __align__(16) __half g_P[BATCH * SEQ * RNK];
__device__ __align__(16) __half g_xh[(size_t)BATCH * SEQ * DIM];
__device__ __align__(16) __half g_Qt[RNK * DIM];          // Q^T * sqrt(log2e)/32, fp16
__device__ __align__(16) float  g_csum[BATCH * DIM];
__device__ __align__(16) float  g_cpart[32][BATCH * DIM];

// ---------------- helpers ----------------
__device__ __forceinline__ uint32_t smem_u32(const void* p) {
    uint32_t a;
    asm("{ .reg .u64 t; cvta.to.shared.u64 t, %1; cvt.u32.u64 %0, t; }" : "=r"(a) : "l"(p));
    return a;
}
__device__ __forceinline__ void ldsm4(uint32_t* r, uint32_t a) {
    asm volatile("ldmatrix.sync.aligned.m8n8.x4.shared.b16 {%0,%1,%2,%3}, [%4];"
        : "=r"(r[0]), "=r"(r[1]), "=r"(r[2]), "=r"(r[3]) : "r"(a));
}
__device__ __forceinline__ void ldsm4t(uint32_t* r, uint32_t a) {
    asm volatile("ldmatrix.sync.aligned.m8n8.x4.trans.shared.b16 {%0,%1,%2,%3}, [%4];"
        : "=r"(r[0]), "=r"(r[1]), "=r"(r[2]), "=r"(r[3]) : "r"(a));
}
__device__ __forceinline__ void mma16816(float* d, const uint32_t* a, const uint32_t* b) {
    asm volatile(
        "mma.sync.aligned.m16n8k16.row.col.f32.f16.f16.f32 "
        "{%0,%1,%2,%3}, {%4,%5,%6,%7}, {%8,%9}, {%0,%1,%2,%3};"
        : "+f"(d[0]), "+f"(d[1]), "+f"(d[2]), "+f"(d[3])
        : "r"(a[0]), "r"(a[1]), "r"(a[2]), "r"(a[3]), "r"(b[0]), "r"(b[1]));
}
#define CP16(dst, src) \
    asm volatile("cp.async.cg.shared.global [%0], [%1], 16;" :: "r"(dst), "l"(src))
#define CP_COMMIT() asm volatile("cp.async.commit_group;" ::: "memory")
#define CP_WAIT0()  asm volatile("cp.async.wait_group 0;" ::: "memory")

__device__ __forceinline__ uint32_t packh(float a, float b) {
    __half2 h = __floats2half2_rn(a, b);
    return *(uint32_t*)&h;
}

// ---------------------------------------------------------------------------
// Fused cvt + csum: x fp32 -> fp16, and per-128-row-chunk column sums.
// ---------------------------------------------------------------------------
__global__ __launch_bounds__(256)
void cvtsum_kernel(const float* __restrict__ x) {
    const int t = threadIdx.x;
    const int sc = blockIdx.x, b = blockIdx.y;
    const float* xp = x + ((size_t)b * SEQ + (size_t)sc * 128) * DIM + 4 * t;
    __half* op = g_xh + ((size_t)b * SEQ + (size_t)sc * 128) * DIM + 4 * t;
    float s0 = 0.f, s1 = 0.f, s2 = 0.f, s3 = 0.f;
#pragma unroll 4
    for (int r = 0; r < 128; r++) {
        float4 v = *(const float4*)(xp + (size_t)r * DIM);
        s0 += v.x; s1 += v.y; s2 += v.z; s3 += v.w;
        *(uint2*)(op + (size_t)r * DIM) = make_uint2(packh(v.x, v.y), packh(v.z, v.w));
    }
    float* cp = g_cpart[sc] + b * DIM + 4 * t;
    cp[0] = s0; cp[1] = s1; cp[2] = s2; cp[3] = s3;
}
__global__ __launch_bounds__(256)
void csum2_kernel() {
    const int idx = blockIdx.x * 256 + threadIdx.x;
    float s = 0.f;
#pragma unroll
    for (int c = 0; c < 32; c++) s += g_cpart[c][idx];
    g_csum[idx] = s;
}

// ---------------------------------------------------------------------------
// qprep: Q -> g_Qt [64 n][1024 k] fp16, scaled by sqrt(log2 e)/32
// ---------------------------------------------------------------------------
__global__ __launch_bounds__(256)
void qprep_kernel(const float* __restrict__ Q) {
    __shared__ float ts[64][65];
    const int t = threadIdx.x;
    const int k0 = blockIdx.x * 64;
    const int r = t >> 2, cb = (t & 3) << 4;
    const float SC = 0.037535075274576556f;   // sqrt(log2 e) / 32
    const float* qp = Q + (size_t)(k0 + r) * RNK + cb;
#pragma unroll
    for (int m = 0; m < 4; m++) {
        float4 v = *(const float4*)(qp + 4 * m);
        ts[r][cb + 4 * m + 0] = v.x * SC;
        ts[r][cb + 4 * m + 1] = v.y * SC;
        ts[r][cb + 4 * m + 2] = v.z * SC;
        ts[r][cb + 4 * m + 3] = v.w * SC;
    }
    __syncthreads();
    __half* o = g_Qt + (size_t)r * DIM + k0 + cb;
#pragma unroll
    for (int m = 0; m < 2; m++) {
        uint32_t w[4];
#pragma unroll
        for (int p = 0; p < 4; p++)
            w[p] = packh(ts[cb + 8 * m + 2 * p][r], ts[cb + 8 * m + 2 * p + 1][r]);
        *(uint4*)(o + 8 * m) = make_uint4(w[0], w[1], w[2], w[3]);
    }
}

// ---------------------------------------------------------------------------
// projH: P = x_h @ Qt^T via HMMA
// ---------------------------------------------------------------------------
#define POFF_X 0
#define POFF_Q 32768
#define PSM_TOTAL 49152

__global__ __launch_bounds__(256, 2)
void projH_kernel() {
    extern __shared__ char sm[];
    const uint32_t smb = smem_u32(sm);
    const int t = threadIdx.x;
    const int warp = t >> 5, lane = t & 31;
    const int row0 = blockIdx.x * 128;
    const int q0 = warp * 16;
    const int tg = lane & 3, g = lane >> 2;
    const int i7 = lane & 7, grp = lane >> 3;

    {
#pragma unroll
        for (int m = 0; m < 4; m++) {
            int idx = t + 256 * m;
            int row = idx >> 3, ch = idx & 7;
            uint32_t dsw = row * 128 + (((uint32_t)(ch ^ (row & 7))) << 4);
            CP16(smb + POFF_X + dsw, g_xh + (size_t)(row0 + row) * DIM + ch * 8);
        }
#pragma unroll
        for (int m = 0; m < 2; m++) {
            int idx = t + 256 * m;
            int row = idx >> 3, ch = idx & 7;
            uint32_t dsw = row * 128 + (((uint32_t)(ch ^ (row & 7))) << 4);
            CP16(smb + POFF_Q + dsw, g_Qt + (size_t)row * DIM + ch * 8);
        }
        CP_COMMIT();
    }

    const uint32_t rowA = q0 + i7 + ((grp & 1) << 3);
    const uint32_t cselA = grp >> 1;
    const uint32_t rowB = i7 + ((grp >> 1) << 3);
    const uint32_t cselB = grp & 1;

    float S[8][4];
#pragma unroll
    for (int n = 0; n < 8; n++)
#pragma unroll
        for (int e = 0; e < 4; e++) S[n][e] = 0.f;

    for (int c = 0; c < 16; c++) {
        const int buf = c & 1;
        CP_WAIT0();
        __syncthreads();
        if (c + 1 < 16) {
            const int kc = (c + 1) * 64;
            const int bo = buf ^ 1;
#pragma unroll
            for (int m = 0; m < 4; m++) {
                int idx = t + 256 * m;
                int row = idx >> 3, ch = idx & 7;
                uint32_t dsw = row * 128 + (((uint32_t)(ch ^ (row & 7))) << 4);
                CP16(smb + POFF_X + bo * 16384 + dsw,
                     g_xh + (size_t)(row0 + row) * DIM + kc + ch * 8);
            }
#pragma unroll
            for (int m = 0; m < 2; m++) {
                int idx = t + 256 * m;
                int row = idx >> 3, ch = idx & 7;
                uint32_t dsw = row * 128 + (((uint32_t)(ch ^ (row & 7))) << 4);
                CP16(smb + POFF_Q + bo * 8192 + dsw,
                     g_Qt + (size_t)row * DIM + kc + ch * 8);
            }
            CP_COMMIT();
        }
        const uint32_t xb = smb + POFF_X + buf * 16384;
        const uint32_t qb = smb + POFF_Q + buf * 8192;
#pragma unroll
        for (int kt = 0; kt < 4; kt++) {
            uint32_t ah[4];
            ldsm4(ah, xb + rowA * 128 + ((((kt << 1) + cselA) ^ i7) << 4));
#pragma unroll
            for (int np = 0; np < 4; np++) {
                uint32_t bh[4];
                ldsm4(bh, qb + ((np << 4) + rowB) * 128
                          + ((((kt << 1) + cselB) ^ i7) << 4));
                mma16816(S[2 * np],     ah, bh + 0);
                mma16816(S[2 * np + 1], ah, bh + 2);
            }
        }
        __syncthreads();
    }

    const int row = row0 + q0 + g;
#pragma unroll
    for (int j = 0; j < 8; j++) {
        const int nb = (j >> 1) * 16 + (j & 1) * 8;
        *(uint32_t*)&g_P[(size_t)row * RNK + nb + 2 * tg] = packh(S[j][0], S[j][1]);
        *(uint32_t*)&g_P[(size_t)(row + 8) * RNK + nb + 2 * tg] = packh(S[j][2], S[j][3]);
    }
}

// ---------------------------------------------------------------------------
// Flash attention, fp16 HMMA, KB=128 buffers with two 64-key subtiles.
// Softmax via ex2.approx.f16x2 (halved MUFU).  Warp tile 16q x 256d.
// grid (32 qtiles, 4 d-slices, 8 batches), 256 threads.
// smem: PQ 16K | PK 2x16K | V 2x64K = 176K
// ---------------------------------------------------------------------------
#define OFF_PQ   0
#define OFF_PK   16384
#define OFF_V    49152
#define SMEM_TOTAL 180224

__global__ __launch_bounds__(256, 1)
void attn_kernel(float* __restrict__ out) {
    extern __shared__ char sm[];
    const uint32_t smb = smem_u32(sm);
    const int t = threadIdx.x;
    const int warp = t >> 5, lane = t & 31;
    const int qb = blockIdx.x, z = blockIdx.y, b = blockIdx.z;
    const int q0 = warp * 16;
    const int tg = lane & 3, g = lane >> 2;
    const int i7 = lane & 7, grp = lane >> 3;

    const __half* pk_g = g_P + (size_t)b * SEQ * RNK;
    const __half* vh_g = g_xh + (size_t)b * SEQ * DIM + (size_t)z * 256;

    // ---- load Pq tile [128 q][64 r] into smem (swizzled) ----
#pragma unroll
    for (int m = 0; m < 4; m++) {
        int idx = t + 256 * m;
        int row = idx >> 3, ch = idx & 7;
        size_t src = ((size_t)b * SEQ + (size_t)qb * 128 + row) * RNK + ch * 8;
        uint32_t dst = row * 128 + (((uint32_t)(ch ^ (row & 7))) << 4);
        *(uint4*)(sm + OFF_PQ + dst) = *(const uint4*)(g_P + src);
    }
    // ---- prefetch tile 0 (128 keys) ----
    {
#pragma unroll
        for (int m = 0; m < 4; m++) {
            int idx = t + 256 * m;
            int row = idx >> 3, ch = idx & 7;
            uint32_t dsw = row * 128 + (((uint32_t)(ch ^ (row & 7))) << 4);
            CP16(smb + OFF_PK + dsw, pk_g + (size_t)row * RNK + ch * 8);
        }
#pragma unroll
        for (int m = 0; m < 16; m++) {
            int idx = t + 256 * m;
            int row = idx >> 5, ch = idx & 31;
            uint32_t dsw = row * 512 + (((uint32_t)(ch ^ (row & 7))) << 4);
            CP16(smb + OFF_V + dsw, vh_g + (size_t)row * DIM + ch * 8);
        }
        CP_COMMIT();
    }
    __syncthreads();

    // ---- hoist Pq A-fragments into registers ----
    const uint32_t rowA = q0 + i7 + ((grp & 1) << 3);
    const uint32_t cselA = grp >> 1;
    uint32_t aReg[4][4];
#pragma unroll
    for (int kt = 0; kt < 4; kt++)
        ldsm4(aReg[kt], smb + OFF_PQ + rowA * 128 + ((((kt << 1) + cselA) ^ i7) << 4));

    float Y[32][4];
#pragma unroll
    for (int n = 0; n < 32; n++)
#pragma unroll
        for (int e = 0; e < 4; e++) Y[n][e] = 0.f;
    float rl = 0.f, rh = 0.f;

    const uint32_t rowB = i7 + ((grp >> 1) << 3);
    const uint32_t cselB = grp & 1;
    const uint32_t rowV = i7 + ((grp & 1) << 3);
    const uint32_t cselV = grp >> 1;
    const __half2 ONE2 = __floats2half2_rn(1.f, 1.f);

    for (int it = 0; it < NIT; it++) {
        const int buf = it & 1;
        CP_WAIT0();
        __syncthreads();

        // prefetch tile it+1 (overlaps compute)
        if (it + 1 < NIT) {
            const int k0n = (it + 1) * KB;
            const int bo = buf ^ 1;
#pragma unroll
            for (int m = 0; m < 4; m++) {
                int idx = t + 256 * m;
                int row = idx >> 3, ch = idx & 7;
                uint32_t dsw = row * 128 + (((uint32_t)(ch ^ (row & 7))) << 4);
                CP16(smb + OFF_PK + bo * 16384 + dsw,
                     pk_g + (size_t)(k0n + row) * RNK + ch * 8);
            }
#pragma unroll
            for (int m = 0; m < 16; m++) {
                int idx = t + 256 * m;
                int row = idx >> 5, ch = idx & 31;
                uint32_t dsw = row * 512 + (((uint32_t)(ch ^ (row & 7))) << 4);
                CP16(smb + OFF_V + bo * 65536 + dsw,
                     vh_g + (size_t)(k0n + row) * DIM + ch * 8);
            }
            CP_COMMIT();
        }

        // ---- two 64-key subtiles within the buffer ----
#pragma unroll
        for (int sub = 0; sub < 2; sub++) {
            const uint32_t pkBase = smb + OFF_PK + buf * 16384 + sub * 8192;
            const uint32_t vBase  = smb + OFF_V  + buf * 65536 + sub * 32768;

            // QK^T (single combo; logits pre-scaled by log2 e)
            float S[8][4];
#pragma unroll
            for (int n = 0; n < 8; n++)
#pragma unroll
                for (int e = 0; e < 4; e++) S[n][e] = 0.f;

#pragma unroll
            for (int kt = 0; kt < 4; kt++) {
#pragma unroll
                for (int np = 0; np < 4; np++) {
                    uint32_t bh[4];
                    ldsm4(bh, pkBase + ((np << 4) + rowB) * 128
                              + ((((kt << 1) + cselB) ^ i7) << 4));
                    mma16816(S[2 * np],     aReg[kt], bh + 0);
                    mma16816(S[2 * np + 1], aReg[kt], bh + 2);
                }
            }

            // ---- per-kt: fp16x2 softmax (half the MUFU ops) + PV mma ----
#pragma unroll
            for (int kt = 0; kt < 4; kt++) {
                const int n0 = 2 * kt;
                __half2 t0 = __floats2half2_rn(S[n0][0],     S[n0][1]);
                __half2 t1 = __floats2half2_rn(S[n0][2],     S[n0][3]);
                __half2 t2 = __floats2half2_rn(S[n0 + 1][0], S[n0 + 1][1]);
                __half2 t3 = __floats2half2_rn(S[n0 + 1][2], S[n0 + 1][3]);
                __half2 p0 = h2exp2(t0);
                __half2 p1 = h2exp2(t1);
                __half2 p2 = h2exp2(t2);
                __half2 p3 = h2exp2(t3);
                float2 f0 = __half22float2(p0);
                float2 f1 = __half22float2(p1);
                float2 f2 = __half22float2(p2);
                float2 f3 = __half22float2(p3);
                rl += (f0.x + f0.y) + (f2.x + f2.y);
                rh += (f1.x + f1.y) + (f3.x + f3.y);
                __half2 q0h = __hsub2(p0, ONE2);
                __half2 q1h = __hsub2(p1, ONE2);
                __half2 q2h = __hsub2(p2, ONE2);
                __half2 q3h = __hsub2(p3, ONE2);
                uint32_t Ph[4];
                Ph[0] = *(uint32_t*)&q0h;
                Ph[1] = *(uint32_t*)&q1h;
                Ph[2] = *(uint32_t*)&q2h;
                Ph[3] = *(uint32_t*)&q3h;

                uint32_t vrow = vBase + ((kt << 4) + rowV) * 512;
#pragma unroll
                for (int np = 0; np < 16; np++) {
                    uint32_t bh[4];
                    ldsm4t(bh, vrow + ((((np << 1) + cselV) ^ i7) << 4));
                    mma16816(Y[2 * np],     Ph, bh + 0);
                    mma16816(Y[2 * np + 1], Ph, bh + 2);
                }
            }
        }
    }

    // ---- single row-sum reduction at the end ----
    rl += __shfl_xor_sync(0xffffffffu, rl, 1);
    rl += __shfl_xor_sync(0xffffffffu, rl, 2);
    rh += __shfl_xor_sync(0xffffffffu, rh, 1);
    rh += __shfl_xor_sync(0xffffffffu, rh, 2);

    // ---- epilogue: y = (csum + Ydot) / l ----
    const float il = 1.0f / rl;
    const float ih = 1.0f / rh;
    const int rlo = qb * 128 + q0 + g;
    const float* cs_base = g_csum + b * DIM + z * 256 + 2 * tg;
    float* o_lo = out + ((size_t)b * SEQ + rlo) * DIM + (size_t)z * 256 + 2 * tg;
    float* o_hi = o_lo + (size_t)8 * DIM;
#pragma unroll
    for (int n = 0; n < 32; n++) {
        float2 cs = *(const float2*)(cs_base + 8 * n);
        float2 p;
        p.x = (Y[n][0] + cs.x) * il; p.y = (Y[n][1] + cs.y) * il;
        *(float2*)(o_lo + 8 * n) = p;
        p.x = (Y[n][2] + cs.x) * ih; p.y = (Y[n][3] + cs.y) * ih;
        *(float2*)(o_hi + 8 * n) = p;
    }
}

// ---------------------------------------------------------------------------
extern "C" void kernel_launch(void* const* d_in, const int* in_sizes, int n_in,
                              void* d_out, int out_size) {
    const float* x = (const float*)d_in[0];
    const float* Q = (const float*)d_in[1];
    float* out = (float*)d_out;

    cudaFuncSetAttribute(attn_kernel, cudaFuncAttributeMaxDynamicSharedMemorySize,
                         SMEM_TOTAL);
    cudaFuncSetAttribute(projH_kernel, cudaFuncAttributeMaxDynamicSharedMemorySize,
                         PSM_TOTAL);

    cvtsum_kernel<<<dim3(SEQ / 128, BATCH), 256>>>(x);
    qprep_kernel<<<DIM / 64, 256>>>(Q);
    projH_kernel<<<BATCH * SEQ / 128, 256, PSM_TOTAL>>>();
    csum2_kernel<<<BATCH * DIM / 256, 256>>>();
    attn_kernel<<<dim3(SEQ / 128, DIM / 256, BATCH), 256, SMEM_TOTAL>>>(out);
}